// round 9
// baseline (speedup 1.0000x reference)
#include <cuda_runtime.h>
#include <cuda_bf16.h>
#include <cstdint>

// Problem constants
#define NB   4
#define NY   16384
#define NX   4096
#define CY   128
#define CX   256
#define CIN0 384          // CY + CX
#define C1   512
#define C2   256
#define C3   128
#define KNN_K 3
#define EPSW  1e-8f
#define BNEPS 1e-5f
#define NTOT (NB * NY)          // 65536 points
#define PTILES (NTOT / 128)     // 512 point tiles

// ---------------- scratch (device globals; no allocation) ----------------
__device__ int            g_idx[(size_t)NTOT * KNN_K];
__device__ float          g_wts[(size_t)NTOT * KNN_K];
__device__ unsigned short g_x1h[(size_t)NTOT * CIN0], g_x1l[(size_t)NTOT * CIN0];
__device__ unsigned short g_x2h[(size_t)NTOT * C1],   g_x2l[(size_t)NTOT * C1];
__device__ unsigned short g_x3h[(size_t)NTOT * C2],   g_x3l[(size_t)NTOT * C2];
__device__ float          g_z1[(size_t)NTOT * C1];
__device__ float          g_z2[(size_t)NTOT * C2];
__device__ float          g_z3[(size_t)NTOT * C3];
__device__ unsigned short g_w1h[C1 * CIN0], g_w1l[C1 * CIN0];
__device__ unsigned short g_w2h[C2 * C1],   g_w2l[C2 * C1];
__device__ unsigned short g_w3h[C3 * C2],   g_w3l[C3 * C2];
__device__ float          g_ps1[PTILES * C1], g_ps2[PTILES * C1];
__device__ float          g_sc1[C1], g_sh1[C1];
__device__ float          g_sc2[C2], g_sh2[C2];
__device__ float          g_sc3[C3], g_sh3[C3];

// ================= helpers (baseline PTX only — valid on plain sm_103) ====
__device__ __forceinline__ uint32_t smem_to_u32(const void* p) {
    uint32_t a;
    asm("{ .reg .u64 t; cvta.to.shared.u64 t, %1; cvt.u32.u64 %0, t; }" : "=r"(a) : "l"(p));
    return a;
}
__device__ __forceinline__ void cp_async16(uint32_t dst, const void* src) {
    asm volatile("cp.async.ca.shared.global [%0], [%1], 16;" :: "r"(dst), "l"(src));
}
__device__ __forceinline__ void cp_async_commit() {
    asm volatile("cp.async.commit_group;" ::: "memory");
}
template <int N>
__device__ __forceinline__ void cp_async_wait() {
    asm volatile("cp.async.wait_group %0;" :: "n"(N) : "memory");
}
__device__ __forceinline__ void ldm_x4(uint32_t* r, uint32_t addr) {
    asm volatile("ldmatrix.sync.aligned.m8n8.x4.shared.b16 {%0,%1,%2,%3}, [%4];"
                 : "=r"(r[0]), "=r"(r[1]), "=r"(r[2]), "=r"(r[3]) : "r"(addr));
}
__device__ __forceinline__ void ldm_x2(uint32_t* r, uint32_t addr) {
    asm volatile("ldmatrix.sync.aligned.m8n8.x2.shared.b16 {%0,%1}, [%2];"
                 : "=r"(r[0]), "=r"(r[1]) : "r"(addr));
}
__device__ __forceinline__ void mma16816(float* d, const uint32_t* a, const uint32_t* b) {
    asm volatile("mma.sync.aligned.m16n8k16.row.col.f32.bf16.bf16.f32 "
                 "{%0,%1,%2,%3}, {%4,%5,%6,%7}, {%8,%9}, {%0,%1,%2,%3};"
                 : "+f"(d[0]), "+f"(d[1]), "+f"(d[2]), "+f"(d[3])
                 : "r"(a[0]), "r"(a[1]), "r"(a[2]), "r"(a[3]), "r"(b[0]), "r"(b[1]));
}
__device__ __forceinline__ void split_bf16(float v, unsigned short& hi, unsigned short& lo) {
    __nv_bfloat16 h = __float2bfloat16_rn(v);
    float hv = __bfloat162float(h);
    __nv_bfloat16 l = __float2bfloat16_rn(v - hv);
    hi = reinterpret_cast<unsigned short&>(h);
    lo = reinterpret_cast<unsigned short&>(l);
}

// ---------------- KNN (numerics frozen — matches reference op-for-op) ----------------
__global__ __launch_bounds__(256) void knn_kernel(const float* __restrict__ yp,
                                                  const float* __restrict__ xp) {
    __shared__ float4 xs[2048];
    const int b = blockIdx.y;
    const int n = blockIdx.x * 256 + threadIdx.x;

    const float* ypt = yp + ((size_t)b * NY + n) * 3;
    const float yx = ypt[0], yy = ypt[1], yz = ypt[2];
    const float sy = __fadd_rn(__fadd_rn(__fmul_rn(yx, yx), __fmul_rn(yy, yy)),
                               __fmul_rn(yz, yz));

    float d0 = 3.4e38f, d1 = 3.4e38f, d2 = 3.4e38f;
    int   i0 = 0, i1 = 0, i2 = 0;

    for (int h = 0; h < 2; ++h) {
        const float* xpb = xp + ((size_t)b * NX + h * 2048) * 3;
        for (int t = threadIdx.x; t < 2048; t += 256) {
            float ax = xpb[t * 3 + 0];
            float ay = xpb[t * 3 + 1];
            float az = xpb[t * 3 + 2];
            float sx = __fadd_rn(__fadd_rn(__fmul_rn(ax, ax), __fmul_rn(ay, ay)),
                                 __fmul_rn(az, az));
            xs[t] = make_float4(ax, ay, az, sx);
        }
        __syncthreads();
        const int base = h * 2048;
#pragma unroll 4
        for (int j = 0; j < 2048; ++j) {
            float4 p = xs[j];
            float dot = __fmaf_rn(yz, p.z, __fmaf_rn(yy, p.y, __fmul_rn(yx, p.x)));
            float t = __fsub_rn(__fadd_rn(sy, p.w), __fmul_rn(2.f, dot));
            if (t < d2) {
                int gi = base + j;
                if (t < d1) {
                    d2 = d1; i2 = i1;
                    if (t < d0) { d1 = d0; i1 = i0; d0 = t; i0 = gi; }
                    else        { d1 = t;  i1 = gi; }
                } else { d2 = t; i2 = gi; }
            }
        }
        __syncthreads();
    }

    float w0 = __fdiv_rn(1.f, __fadd_rn(d0, EPSW));
    float w1 = __fdiv_rn(1.f, __fadd_rn(d1, EPSW));
    float w2 = __fdiv_rn(1.f, __fadd_rn(d2, EPSW));
    float ws = __fadd_rn(__fadd_rn(w0, w1), w2);
    const size_t o = ((size_t)b * NY + n) * 3;
    g_idx[o + 0] = i0; g_idx[o + 1] = i1; g_idx[o + 2] = i2;
    g_wts[o + 0] = __fdiv_rn(w0, ws);
    g_wts[o + 1] = __fdiv_rn(w1, ws);
    g_wts[o + 2] = __fdiv_rn(w2, ws);
}

// ---------------- interp + concat -> X1 bf16 hi/lo, point-major [n][384] ----------------
__global__ __launch_bounds__(384) void interp_split_kernel(const float* __restrict__ yf,
                                                           const float* __restrict__ xf) {
    const int tid = threadIdx.x;            // 0..383 (== channel)
    size_t n = (size_t)blockIdx.x * 4;
    for (int r = 0; r < 4; ++r, ++n) {
        float v;
        if (tid < CY) {
            v = yf[n * CY + tid];
        } else {
            const size_t o = n * 3;
            float w0 = g_wts[o], w1 = g_wts[o + 1], w2 = g_wts[o + 2];
            int   j0 = g_idx[o], j1 = g_idx[o + 1], j2 = g_idx[o + 2];
            const int b = (int)(n >> 14);
            const float* xfb = xf + (size_t)b * NX * CX;
            const int c = tid - CY;
            float t0 = __fmul_rn(xfb[(size_t)j0 * CX + c], w0);
            float t1 = __fmul_rn(xfb[(size_t)j1 * CX + c], w1);
            float t2 = __fmul_rn(xfb[(size_t)j2 * CX + c], w2);
            v = __fadd_rn(__fadd_rn(t0, t1), t2);
        }
        unsigned short hi, lo;
        split_bf16(v, hi, lo);
        g_x1h[n * CIN0 + tid] = hi;
        g_x1l[n * CIN0 + tid] = lo;
    }
}

// ---------------- weight fp32 -> bf16 hi/lo ----------------
__global__ void prep_w_kernel(const float* __restrict__ W, unsigned short* __restrict__ hi,
                              unsigned short* __restrict__ lo, int n) {
    int i = blockIdx.x * 256 + threadIdx.x;
    if (i < n) {
        unsigned short h, l;
        split_bf16(W[i], h, l);
        hi[i] = h; lo[i] = l;
    }
}

// ---------------- BN+ReLU+split prepass: Z fp32 [n][C] -> X bf16 hi/lo [n][C] ----------------
template <int C>
__global__ __launch_bounds__(256) void prep_x_kernel(const float* __restrict__ Z,
                                                     const float* __restrict__ sc,
                                                     const float* __restrict__ sh,
                                                     unsigned short* __restrict__ Xh,
                                                     unsigned short* __restrict__ Xl) {
    size_t i = (size_t)blockIdx.x * 256 + threadIdx.x;   // float4 index
    int c0 = (int)((i * 4) & (C - 1));
    float4 v = ((const float4*)Z)[i];
    float r0 = fmaxf(fmaf(v.x, sc[c0 + 0], sh[c0 + 0]), 0.f);
    float r1 = fmaxf(fmaf(v.y, sc[c0 + 1], sh[c0 + 1]), 0.f);
    float r2 = fmaxf(fmaf(v.z, sc[c0 + 2], sh[c0 + 2]), 0.f);
    float r3 = fmaxf(fmaf(v.w, sc[c0 + 3], sh[c0 + 3]), 0.f);
    ushort4 h, l;
    split_bf16(r0, h.x, l.x); split_bf16(r1, h.y, l.y);
    split_bf16(r2, h.z, l.z); split_bf16(r3, h.w, l.w);
    ((ushort4*)Xh)[i] = h;
    ((ushort4*)Xl)[i] = l;
}

// ---------------- mma.sync split-bf16 GEMM, 2-stage cp.async pipeline ----------------
// Z[n][m] = sum_k X[n][k]*W[m][k] + bias[m];  X/W = hi+lo bf16, 3 passes (HH, HL, LH).
// CTA: 128 points x 128 channels. 8 warps (2 point x 4 channel), warp tile 64x32.
// K chunk = 32. SMEM rows padded to 40 bf16 (80 B). Double-buffered (2 stages).
#define TSTRIDE 80            // bytes per SMEM row
#define TILE_B  10240         // bytes per operand tile (128 rows * 80)
#define STAGE_B (4 * TILE_B)  // 40960 bytes per stage (Xh, Xl, Wh, Wl)
#define XH_OFF  0
#define XL_OFF  10240
#define WH_OFF  20480
#define WL_OFF  30720

template <int KD, int MTOT>
__global__ __launch_bounds__(256) void gemm_mma_kernel(
    const unsigned short* __restrict__ Xh, const unsigned short* __restrict__ Xl,
    const unsigned short* __restrict__ Wh, const unsigned short* __restrict__ Wl,
    const float* __restrict__ bias, float* __restrict__ Z,
    float* __restrict__ ps1, float* __restrict__ ps2) {
    constexpr int CHUNKS = KD / 32;
    extern __shared__ __align__(16) unsigned char stile[];   // 2 * STAGE_B
    __shared__ float sred[8][64];            // [warp][ch 0..31 = s1, 32..63 = s2]
    const uint32_t sm = smem_to_u32(stile);

    const int tid = threadIdx.x;
    const int wid = tid >> 5, lane = tid & 31;
    const int wi = wid >> 2;                 // point-warp (0..1)
    const int wj = wid & 3;                  // channel-warp (0..3)
    const int m0 = blockIdx.x * 128;         // channel base
    const size_t n0 = (size_t)blockIdx.y * 128;  // point base

    const unsigned short* srcs[4] = {
        Xh + n0 * KD, Xl + n0 * KD, Wh + (size_t)m0 * KD, Wl + (size_t)m0 * KD };

    float acc[4][4][4];
#pragma unroll
    for (int mi = 0; mi < 4; ++mi)
#pragma unroll
        for (int ni = 0; ni < 4; ++ni)
#pragma unroll
            for (int q = 0; q < 4; ++q) acc[mi][ni][q] = 0.f;

    // per-thread load coords (2 x 16B per operand tile)
    const int lrow0 = tid >> 2,            lks0 = tid & 3;
    const int lrow1 = (tid + 256) >> 2,    lks1 = (tid + 256) & 3;

    // issue loads for chunk c into stage buffer
    auto issue_chunk = [&](int c) {
        const uint32_t sb = sm + (uint32_t)(c & 1) * STAGE_B;
        const int k0 = c * 32;
#pragma unroll
        for (int t = 0; t < 4; ++t) {
            const unsigned short* src = srcs[t];
            const uint32_t dstb = sb + t * TILE_B;
            cp_async16(dstb + lrow0 * TSTRIDE + lks0 * 16,
                       src + (size_t)lrow0 * KD + k0 + lks0 * 8);
            cp_async16(dstb + lrow1 * TSTRIDE + lks1 * 16,
                       src + (size_t)lrow1 * KD + k0 + lks1 * 8);
        }
        cp_async_commit();
    };

    // precomputed ldmatrix lane addresses (byte offsets w/o stage/kstep)
    const uint32_t aRow = (uint32_t)(wi * 64 + (lane & 7) + ((lane >> 3) & 1) * 8);
    const uint32_t aK   = (uint32_t)((lane >> 4) * 16);
    const uint32_t bRow = (uint32_t)(wj * 32 + (lane & 7));
    const uint32_t bK   = (uint32_t)(((lane >> 3) & 1) * 16);

    issue_chunk(0);
    for (int ck = 0; ck < CHUNKS; ++ck) {
        if (ck + 1 < CHUNKS) {
            issue_chunk(ck + 1);
            cp_async_wait<1>();      // chunk ck complete (latest group may be in flight)
        } else {
            cp_async_wait<0>();
        }
        __syncthreads();             // chunk ck visible to all warps

        const uint32_t sb = sm + (uint32_t)(ck & 1) * STAGE_B;
#pragma unroll
        for (int p = 0; p < 3; ++p) {
            const uint32_t aBase = sb + (p == 2 ? XL_OFF : XH_OFF);
            const uint32_t bBase = sb + (p == 1 ? WL_OFF : WH_OFF);
#pragma unroll
            for (int kk = 0; kk < 2; ++kk) {
                uint32_t afr[4][4], bfr[4][2];
#pragma unroll
                for (int mi = 0; mi < 4; ++mi)
                    ldm_x4(afr[mi], aBase + (aRow + mi * 16) * TSTRIDE + kk * 32 + aK);
#pragma unroll
                for (int ni = 0; ni < 4; ++ni)
                    ldm_x2(bfr[ni], bBase + (bRow + ni * 8) * TSTRIDE + kk * 32 + bK);
#pragma unroll
                for (int mi = 0; mi < 4; ++mi)
#pragma unroll
                    for (int ni = 0; ni < 4; ++ni)
                        mma16816(acc[mi][ni], afr[mi], bfr[ni]);
            }
        }
        __syncthreads();             // all warps done with buffer ck before it is re-filled
    }

    // ---- epilogue: bias add, Z store, deterministic BN partial sums ----
    const int grp = lane >> 2, t4 = lane & 3;
    float s1[8], s2[8];
#pragma unroll
    for (int q = 0; q < 8; ++q) { s1[q] = 0.f; s2[q] = 0.f; }

#pragma unroll
    for (int ni = 0; ni < 4; ++ni) {
        const int j = m0 + wj * 32 + ni * 8 + 2 * t4;
        const float bv0 = bias[j], bv1 = bias[j + 1];
#pragma unroll
        for (int mi = 0; mi < 4; ++mi) {
            const size_t r0 = n0 + wi * 64 + mi * 16 + grp;
            const size_t r1 = r0 + 8;
            float z0 = acc[mi][ni][0] + bv0;
            float z1 = acc[mi][ni][1] + bv1;
            float z2 = acc[mi][ni][2] + bv0;
            float z3 = acc[mi][ni][3] + bv1;
            *(float2*)(Z + r0 * MTOT + j) = make_float2(z0, z1);
            *(float2*)(Z + r1 * MTOT + j) = make_float2(z2, z3);
            s1[ni * 2 + 0] += z0 + z2;
            s1[ni * 2 + 1] += z1 + z3;
            s2[ni * 2 + 0] = fmaf(z0, z0, fmaf(z2, z2, s2[ni * 2 + 0]));
            s2[ni * 2 + 1] = fmaf(z1, z1, fmaf(z3, z3, s2[ni * 2 + 1]));
        }
    }
    // reduce over the 8 groups (rows) within the warp
#pragma unroll
    for (int off = 16; off >= 4; off >>= 1)
#pragma unroll
        for (int q = 0; q < 8; ++q) {
            s1[q] += __shfl_down_sync(0xFFFFFFFFu, s1[q], off);
            s2[q] += __shfl_down_sync(0xFFFFFFFFu, s2[q], off);
        }
    if (lane < 4) {
#pragma unroll
        for (int ni = 0; ni < 4; ++ni)
#pragma unroll
            for (int c = 0; c < 2; ++c) {
                sred[wid][ni * 8 + 2 * lane + c]      = s1[ni * 2 + c];
                sred[wid][32 + ni * 8 + 2 * lane + c] = s2[ni * 2 + c];
            }
    }
    __syncthreads();
    if (tid < 128) {
        const int wjj = tid >> 5, cl = tid & 31;
        float a1 = sred[wjj][cl]      + sred[wjj + 4][cl];
        float a2 = sred[wjj][32 + cl] + sred[wjj + 4][32 + cl];
        ps1[(size_t)blockIdx.y * MTOT + m0 + tid] = a1;
        ps2[(size_t)blockIdx.y * MTOT + m0 + tid] = a2;
    }
}

// ---------------- BN finalize: reduce partials -> scale/shift ----------------
__global__ __launch_bounds__(256) void bn_finalize_kernel(const float* __restrict__ ps1,
                                                          const float* __restrict__ ps2,
                                                          const float* __restrict__ g,
                                                          const float* __restrict__ be,
                                                          float* __restrict__ sc,
                                                          float* __restrict__ sh, int M) {
    const int m = blockIdx.x;
    const int tid = threadIdx.x;
    float s1 = 0.f, s2 = 0.f;
    for (int t = tid; t < PTILES; t += 256) {
        s1 += ps1[(size_t)t * M + m];
        s2 += ps2[(size_t)t * M + m];
    }
    __shared__ float r1[8], r2[8];
#pragma unroll
    for (int off = 16; off; off >>= 1) {
        s1 += __shfl_down_sync(0xFFFFFFFFu, s1, off);
        s2 += __shfl_down_sync(0xFFFFFFFFu, s2, off);
    }
    if ((tid & 31) == 0) { r1[tid >> 5] = s1; r2[tid >> 5] = s2; }
    __syncthreads();
    if (tid < 32) {
        s1 = (tid < 8) ? r1[tid] : 0.f;
        s2 = (tid < 8) ? r2[tid] : 0.f;
#pragma unroll
        for (int off = 4; off; off >>= 1) {
            s1 += __shfl_down_sync(0xFFFFFFFFu, s1, off);
            s2 += __shfl_down_sync(0xFFFFFFFFu, s2, off);
        }
        if (tid == 0) {
            const float inv = 1.f / (float)NTOT;
            float mu  = s1 * inv;
            float var = s2 * inv - mu * mu;
            float r   = rsqrtf(var + BNEPS);
            float s   = r * g[m];
            sc[m] = s;
            sh[m] = be[m] - mu * s;
        }
    }
}

// ---------------- final: BN3+ReLU + transpose [n][128] -> out [b][128][NY] ----------------
__global__ __launch_bounds__(256) void final_kernel(const float* __restrict__ Z3,
                                                    float* __restrict__ out) {
    __shared__ float tile[32][33];
    const int b = blockIdx.z;
    const int n0 = blockIdx.x * 32;
    const int c0 = blockIdx.y * 32;
    const int tx = threadIdx.x, ty = threadIdx.y;   // 32 x 8
    const float sc = g_sc3[c0 + tx], sh = g_sh3[c0 + tx];
#pragma unroll
    for (int r = 0; r < 4; ++r) {
        int n = n0 + ty + 8 * r;
        float v = Z3[((size_t)b * NY + n) * C3 + c0 + tx];
        tile[ty + 8 * r][tx] = fmaxf(fmaf(v, sc, sh), 0.f);
    }
    __syncthreads();
#pragma unroll
    for (int r = 0; r < 4; ++r) {
        int cl = ty + 8 * r;
        out[((size_t)b * C3 + c0 + cl) * NY + n0 + tx] = tile[tx][cl];
    }
}

// ---------------- host launcher ----------------
extern "C" void kernel_launch(void* const* d_in, const int* in_sizes, int n_in,
                              void* d_out, int out_size) {
    (void)in_sizes; (void)n_in; (void)out_size;
    const float* yp = (const float*)d_in[0];
    const float* yf = (const float*)d_in[1];
    const float* xp = (const float*)d_in[2];
    const float* xf = (const float*)d_in[3];
    const float* W1 = (const float*)d_in[4];
    const float* b1 = (const float*)d_in[5];
    const float* g1 = (const float*)d_in[6];
    const float* be1 = (const float*)d_in[7];
    const float* W2 = (const float*)d_in[8];
    const float* b2 = (const float*)d_in[9];
    const float* g2 = (const float*)d_in[10];
    const float* be2 = (const float*)d_in[11];
    const float* W3 = (const float*)d_in[12];
    const float* b3 = (const float*)d_in[13];
    const float* g3 = (const float*)d_in[14];
    const float* be3 = (const float*)d_in[15];
    float* out = (float*)d_out;

    unsigned short *x1h, *x1l, *x2h, *x2l, *x3h, *x3l;
    unsigned short *w1h, *w1l, *w2h, *w2l, *w3h, *w3l;
    float *z1, *z2, *z3, *ps1, *ps2;
    float *sc1, *sh1, *sc2, *sh2, *sc3, *sh3;
    cudaGetSymbolAddress((void**)&x1h, g_x1h); cudaGetSymbolAddress((void**)&x1l, g_x1l);
    cudaGetSymbolAddress((void**)&x2h, g_x2h); cudaGetSymbolAddress((void**)&x2l, g_x2l);
    cudaGetSymbolAddress((void**)&x3h, g_x3h); cudaGetSymbolAddress((void**)&x3l, g_x3l);
    cudaGetSymbolAddress((void**)&w1h, g_w1h); cudaGetSymbolAddress((void**)&w1l, g_w1l);
    cudaGetSymbolAddress((void**)&w2h, g_w2h); cudaGetSymbolAddress((void**)&w2l, g_w2l);
    cudaGetSymbolAddress((void**)&w3h, g_w3h); cudaGetSymbolAddress((void**)&w3l, g_w3l);
    cudaGetSymbolAddress((void**)&z1, g_z1);
    cudaGetSymbolAddress((void**)&z2, g_z2);
    cudaGetSymbolAddress((void**)&z3, g_z3);
    cudaGetSymbolAddress((void**)&ps1, g_ps1); cudaGetSymbolAddress((void**)&ps2, g_ps2);
    cudaGetSymbolAddress((void**)&sc1, g_sc1); cudaGetSymbolAddress((void**)&sh1, g_sh1);
    cudaGetSymbolAddress((void**)&sc2, g_sc2); cudaGetSymbolAddress((void**)&sh2, g_sh2);
    cudaGetSymbolAddress((void**)&sc3, g_sc3); cudaGetSymbolAddress((void**)&sh3, g_sh3);

    const int SMEM_GEMM = 2 * STAGE_B;   // 81920 B dynamic
    cudaFuncSetAttribute(gemm_mma_kernel<CIN0, C1>, cudaFuncAttributeMaxDynamicSharedMemorySize, SMEM_GEMM);
    cudaFuncSetAttribute(gemm_mma_kernel<C1, C2>,  cudaFuncAttributeMaxDynamicSharedMemorySize, SMEM_GEMM);
    cudaFuncSetAttribute(gemm_mma_kernel<C2, C3>,  cudaFuncAttributeMaxDynamicSharedMemorySize, SMEM_GEMM);

    // 1) KNN
    knn_kernel<<<dim3(NY / 256, NB), 256>>>(yp, xp);
    // 2) interp + concat -> X1 hi/lo
    interp_split_kernel<<<NTOT / 4, 384>>>(yf, xf);
    // 3) weight splits
    prep_w_kernel<<<(C1 * CIN0 + 255) / 256, 256>>>(W1, w1h, w1l, C1 * CIN0);
    prep_w_kernel<<<(C2 * C1 + 255) / 256, 256>>>(W2, w2h, w2l, C2 * C1);
    prep_w_kernel<<<(C3 * C2 + 255) / 256, 256>>>(W3, w3h, w3l, C3 * C2);
    // 4) layer 1: X1[384] -> Z1[512]
    gemm_mma_kernel<CIN0, C1><<<dim3(C1 / 128, PTILES), 256, SMEM_GEMM>>>(
        x1h, x1l, w1h, w1l, b1, z1, ps1, ps2);
    bn_finalize_kernel<<<C1, 256>>>(ps1, ps2, g1, be1, sc1, sh1, C1);
    prep_x_kernel<C1><<<(NTOT * C1 / 4) / 256, 256>>>(z1, sc1, sh1, x2h, x2l);
    // 5) layer 2: X2[512] -> Z2[256]
    gemm_mma_kernel<C1, C2><<<dim3(C2 / 128, PTILES), 256, SMEM_GEMM>>>(
        x2h, x2l, w2h, w2l, b2, z2, ps1, ps2);
    bn_finalize_kernel<<<C2, 256>>>(ps1, ps2, g2, be2, sc2, sh2, C2);
    prep_x_kernel<C2><<<(NTOT * C2 / 4) / 256, 256>>>(z2, sc2, sh2, x3h, x3l);
    // 6) layer 3: X3[256] -> Z3[128]
    gemm_mma_kernel<C2, C3><<<dim3(C3 / 128, PTILES), 256, SMEM_GEMM>>>(
        x3h, x3l, w3h, w3l, b3, z3, ps1, ps2);
    bn_finalize_kernel<<<C3, 256>>>(ps1, ps2, g3, be3, sc3, sh3, C3);
    // 7) final BN3+ReLU + transpose to [b][c][n]
    final_kernel<<<dim3(NY / 32, C3 / 32, NB), dim3(32, 8)>>>(z3, out);
}

// round 10
// speedup vs baseline: 1.0163x; 1.0163x over previous
#include <cuda_runtime.h>
#include <cuda_bf16.h>
#include <cstdint>

// Problem constants
#define NB   4
#define NY   16384
#define NX   4096
#define CY   128
#define CX   256
#define CIN0 384          // CY + CX
#define C1   512
#define C2   256
#define C3   128
#define KNN_K 3
#define EPSW  1e-8f
#define BNEPS 1e-5f
#define NTOT (NB * NY)          // 65536 points
#define PTILES (NTOT / 128)     // 512 point tiles

// ---------------- scratch (device globals; no allocation) ----------------
__device__ int            g_idx[(size_t)NTOT * KNN_K];
__device__ float          g_wts[(size_t)NTOT * KNN_K];
__device__ unsigned short g_x1h[(size_t)NTOT * CIN0], g_x1l[(size_t)NTOT * CIN0];
__device__ unsigned short g_x2h[(size_t)NTOT * C1],   g_x2l[(size_t)NTOT * C1];
__device__ unsigned short g_x3h[(size_t)NTOT * C2],   g_x3l[(size_t)NTOT * C2];
__device__ float          g_z1[(size_t)NTOT * C1];
__device__ float          g_z2[(size_t)NTOT * C2];
__device__ float          g_z3[(size_t)NTOT * C3];
__device__ unsigned short g_w1h[C1 * CIN0], g_w1l[C1 * CIN0];
__device__ unsigned short g_w2h[C2 * C1],   g_w2l[C2 * C1];
__device__ unsigned short g_w3h[C3 * C2],   g_w3l[C3 * C2];
__device__ float          g_ps1[PTILES * C1], g_ps2[PTILES * C1];
__device__ float          g_sc1[C1], g_sh1[C1];
__device__ float          g_sc2[C2], g_sh2[C2];
__device__ float          g_sc3[C3], g_sh3[C3];

// ================= helpers (baseline PTX only — valid on plain sm_103) ====
__device__ __forceinline__ uint32_t smem_to_u32(const void* p) {
    uint32_t a;
    asm("{ .reg .u64 t; cvta.to.shared.u64 t, %1; cvt.u32.u64 %0, t; }" : "=r"(a) : "l"(p));
    return a;
}
__device__ __forceinline__ void cp_async16(uint32_t dst, const void* src) {
    asm volatile("cp.async.ca.shared.global [%0], [%1], 16;" :: "r"(dst), "l"(src));
}
__device__ __forceinline__ void cp_async_commit_wait() {
    asm volatile("cp.async.commit_group;" ::: "memory");
    asm volatile("cp.async.wait_group 0;" ::: "memory");
}
__device__ __forceinline__ void ldm_x4(uint32_t* r, uint32_t addr) {
    asm volatile("ldmatrix.sync.aligned.m8n8.x4.shared.b16 {%0,%1,%2,%3}, [%4];"
                 : "=r"(r[0]), "=r"(r[1]), "=r"(r[2]), "=r"(r[3]) : "r"(addr));
}
__device__ __forceinline__ void ldm_x2(uint32_t* r, uint32_t addr) {
    asm volatile("ldmatrix.sync.aligned.m8n8.x2.shared.b16 {%0,%1}, [%2];"
                 : "=r"(r[0]), "=r"(r[1]) : "r"(addr));
}
__device__ __forceinline__ void mma16816(float* d, const uint32_t* a, const uint32_t* b) {
    asm volatile("mma.sync.aligned.m16n8k16.row.col.f32.bf16.bf16.f32 "
                 "{%0,%1,%2,%3}, {%4,%5,%6,%7}, {%8,%9}, {%0,%1,%2,%3};"
                 : "+f"(d[0]), "+f"(d[1]), "+f"(d[2]), "+f"(d[3])
                 : "r"(a[0]), "r"(a[1]), "r"(a[2]), "r"(a[3]), "r"(b[0]), "r"(b[1]));
}
__device__ __forceinline__ void split_bf16(float v, unsigned short& hi, unsigned short& lo) {
    __nv_bfloat16 h = __float2bfloat16_rn(v);
    float hv = __bfloat162float(h);
    __nv_bfloat16 l = __float2bfloat16_rn(v - hv);
    hi = reinterpret_cast<unsigned short&>(h);
    lo = reinterpret_cast<unsigned short&>(l);
}

// ---------------- KNN (numerics frozen — matches reference op-for-op) ----------------
__global__ __launch_bounds__(256) void knn_kernel(const float* __restrict__ yp,
                                                  const float* __restrict__ xp) {
    __shared__ float4 xs[2048];
    const int b = blockIdx.y;
    const int n = blockIdx.x * 256 + threadIdx.x;

    const float* ypt = yp + ((size_t)b * NY + n) * 3;
    const float yx = ypt[0], yy = ypt[1], yz = ypt[2];
    const float sy = __fadd_rn(__fadd_rn(__fmul_rn(yx, yx), __fmul_rn(yy, yy)),
                               __fmul_rn(yz, yz));

    float d0 = 3.4e38f, d1 = 3.4e38f, d2 = 3.4e38f;
    int   i0 = 0, i1 = 0, i2 = 0;

    for (int h = 0; h < 2; ++h) {
        const float* xpb = xp + ((size_t)b * NX + h * 2048) * 3;
        for (int t = threadIdx.x; t < 2048; t += 256) {
            float ax = xpb[t * 3 + 0];
            float ay = xpb[t * 3 + 1];
            float az = xpb[t * 3 + 2];
            float sx = __fadd_rn(__fadd_rn(__fmul_rn(ax, ax), __fmul_rn(ay, ay)),
                                 __fmul_rn(az, az));
            xs[t] = make_float4(ax, ay, az, sx);
        }
        __syncthreads();
        const int base = h * 2048;
#pragma unroll 4
        for (int j = 0; j < 2048; ++j) {
            float4 p = xs[j];
            float dot = __fmaf_rn(yz, p.z, __fmaf_rn(yy, p.y, __fmul_rn(yx, p.x)));
            float t = __fsub_rn(__fadd_rn(sy, p.w), __fmul_rn(2.f, dot));
            if (t < d2) {
                int gi = base + j;
                if (t < d1) {
                    d2 = d1; i2 = i1;
                    if (t < d0) { d1 = d0; i1 = i0; d0 = t; i0 = gi; }
                    else        { d1 = t;  i1 = gi; }
                } else { d2 = t; i2 = gi; }
            }
        }
        __syncthreads();
    }

    float w0 = __fdiv_rn(1.f, __fadd_rn(d0, EPSW));
    float w1 = __fdiv_rn(1.f, __fadd_rn(d1, EPSW));
    float w2 = __fdiv_rn(1.f, __fadd_rn(d2, EPSW));
    float ws = __fadd_rn(__fadd_rn(w0, w1), w2);
    const size_t o = ((size_t)b * NY + n) * 3;
    g_idx[o + 0] = i0; g_idx[o + 1] = i1; g_idx[o + 2] = i2;
    g_wts[o + 0] = __fdiv_rn(w0, ws);
    g_wts[o + 1] = __fdiv_rn(w1, ws);
    g_wts[o + 2] = __fdiv_rn(w2, ws);
}

// ---------------- interp + concat -> X1 bf16 hi/lo, point-major [n][384] ----------------
__global__ __launch_bounds__(384) void interp_split_kernel(const float* __restrict__ yf,
                                                           const float* __restrict__ xf) {
    const int tid = threadIdx.x;            // 0..383 (== channel)
    size_t n = (size_t)blockIdx.x * 4;
    for (int r = 0; r < 4; ++r, ++n) {
        float v;
        if (tid < CY) {
            v = yf[n * CY + tid];
        } else {
            const size_t o = n * 3;
            float w0 = g_wts[o], w1 = g_wts[o + 1], w2 = g_wts[o + 2];
            int   j0 = g_idx[o], j1 = g_idx[o + 1], j2 = g_idx[o + 2];
            const int b = (int)(n >> 14);
            const float* xfb = xf + (size_t)b * NX * CX;
            const int c = tid - CY;
            float t0 = __fmul_rn(xfb[(size_t)j0 * CX + c], w0);
            float t1 = __fmul_rn(xfb[(size_t)j1 * CX + c], w1);
            float t2 = __fmul_rn(xfb[(size_t)j2 * CX + c], w2);
            v = __fadd_rn(__fadd_rn(t0, t1), t2);
        }
        unsigned short hi, lo;
        split_bf16(v, hi, lo);
        g_x1h[n * CIN0 + tid] = hi;
        g_x1l[n * CIN0 + tid] = lo;
    }
}

// ---------------- all weights fp32 -> bf16 hi/lo in ONE launch ----------------
#define NW1 (C1 * CIN0)    // 196608
#define NW2 (C2 * C1)      // 131072
#define NW3 (C3 * C2)      // 32768
#define NWTOT (NW1 + NW2 + NW3)
__global__ __launch_bounds__(256) void prep_w_all_kernel(const float* __restrict__ W1,
                                                         const float* __restrict__ W2,
                                                         const float* __restrict__ W3) {
    int i = blockIdx.x * 256 + threadIdx.x;
    if (i >= NWTOT) return;
    const float* W; unsigned short *hi, *lo; int j;
    if (i < NW1)            { W = W1; hi = g_w1h; lo = g_w1l; j = i; }
    else if (i < NW1 + NW2) { W = W2; hi = g_w2h; lo = g_w2l; j = i - NW1; }
    else                    { W = W3; hi = g_w3h; lo = g_w3l; j = i - NW1 - NW2; }
    unsigned short h, l;
    split_bf16(W[j], h, l);
    hi[j] = h; lo[j] = l;
}

// ---------------- BN+ReLU+split prepass: Z fp32 [n][C] -> X bf16 hi/lo [n][C] ----------------
template <int C>
__global__ __launch_bounds__(256) void prep_x_kernel(const float* __restrict__ Z,
                                                     const float* __restrict__ sc,
                                                     const float* __restrict__ sh,
                                                     unsigned short* __restrict__ Xh,
                                                     unsigned short* __restrict__ Xl) {
    size_t i = (size_t)blockIdx.x * 256 + threadIdx.x;   // float4 index
    int c0 = (int)((i * 4) & (C - 1));
    float4 v = ((const float4*)Z)[i];
    float r0 = fmaxf(fmaf(v.x, sc[c0 + 0], sh[c0 + 0]), 0.f);
    float r1 = fmaxf(fmaf(v.y, sc[c0 + 1], sh[c0 + 1]), 0.f);
    float r2 = fmaxf(fmaf(v.z, sc[c0 + 2], sh[c0 + 2]), 0.f);
    float r3 = fmaxf(fmaf(v.w, sc[c0 + 3], sh[c0 + 3]), 0.f);
    ushort4 h, l;
    split_bf16(r0, h.x, l.x); split_bf16(r1, h.y, l.y);
    split_bf16(r2, h.z, l.z); split_bf16(r3, h.w, l.w);
    ((ushort4*)Xh)[i] = h;
    ((ushort4*)Xl)[i] = l;
}

// ---------------- mma.sync split-bf16 GEMM (single-buffered, best-known R8) ----------------
// Z[n][m] = sum_k X[n][k]*W[m][k] + bias[m];  X/W = hi+lo bf16, 3 passes (HH, HL, LH).
// CTA: 128 points x 128 channels. 8 warps (2 point x 4 channel), warp tile 64x32.
// K chunk = 32. SMEM rows padded to 40 bf16 (80 B).
#define TSTRIDE 80            // bytes per SMEM row
#define TILE_B  10240         // bytes per tile (128 rows * 80)
#define XH_OFF  0
#define XL_OFF  10240
#define WH_OFF  20480
#define WL_OFF  30720

template <int KD, int MTOT>
__global__ __launch_bounds__(256) void gemm_mma_kernel(
    const unsigned short* __restrict__ Xh, const unsigned short* __restrict__ Xl,
    const unsigned short* __restrict__ Wh, const unsigned short* __restrict__ Wl,
    const float* __restrict__ bias, float* __restrict__ Z,
    float* __restrict__ ps1, float* __restrict__ ps2) {
    __shared__ __align__(16) unsigned char stile[4 * TILE_B];
    __shared__ float sred[8][64];            // [warp][ch 0..31 = s1, 32..63 = s2]
    const uint32_t sm = smem_to_u32(stile);

    const int tid = threadIdx.x;
    const int wid = tid >> 5, lane = tid & 31;
    const int wi = wid >> 2;                 // point-warp (0..1)
    const int wj = wid & 3;                  // channel-warp (0..3)
    const int m0 = blockIdx.x * 128;         // channel base
    const size_t n0 = (size_t)blockIdx.y * 128;  // point base

    const unsigned short* srcs[4] = {
        Xh + n0 * KD, Xl + n0 * KD, Wh + (size_t)m0 * KD, Wl + (size_t)m0 * KD };

    float acc[4][4][4];
#pragma unroll
    for (int mi = 0; mi < 4; ++mi)
#pragma unroll
        for (int ni = 0; ni < 4; ++ni)
#pragma unroll
            for (int q = 0; q < 4; ++q) acc[mi][ni][q] = 0.f;

    // precomputed ldmatrix lane addresses (byte offsets w/o kstep)
    const uint32_t aRow = (uint32_t)(wi * 64 + (lane & 7) + ((lane >> 3) & 1) * 8);
    const uint32_t aK   = (uint32_t)((lane >> 4) * 16);
    const uint32_t bRow = (uint32_t)(wj * 32 + (lane & 7));
    const uint32_t bK   = (uint32_t)(((lane >> 3) & 1) * 16);

    for (int ck = 0; ck < KD / 32; ++ck) {
        if (ck) __syncthreads();             // all warps done with prev tile
        const int k0 = ck * 32;
#pragma unroll
        for (int t = 0; t < 4; ++t) {
            const unsigned short* src = srcs[t];
            const uint32_t dstb = sm + t * TILE_B;
#pragma unroll
            for (int q = 0; q < 2; ++q) {
                int idx = tid + q * 256;
                int row = idx >> 2, ks = idx & 3;
                cp_async16(dstb + row * TSTRIDE + ks * 16,
                           src + (size_t)row * KD + k0 + ks * 8);
            }
        }
        cp_async_commit_wait();
        __syncthreads();

#pragma unroll
        for (int p = 0; p < 3; ++p) {
            const uint32_t aBase = sm + (p == 2 ? XL_OFF : XH_OFF);
            const uint32_t bBase = sm + (p == 1 ? WL_OFF : WH_OFF);
#pragma unroll
            for (int kk = 0; kk < 2; ++kk) {
                uint32_t afr[4][4], bfr[4][2];
#pragma unroll
                for (int mi = 0; mi < 4; ++mi)
                    ldm_x4(afr[mi], aBase + (aRow + mi * 16) * TSTRIDE + kk * 32 + aK);
#pragma unroll
                for (int ni = 0; ni < 4; ++ni)
                    ldm_x2(bfr[ni], bBase + (bRow + ni * 8) * TSTRIDE + kk * 32 + bK);
#pragma unroll
                for (int mi = 0; mi < 4; ++mi)
#pragma unroll
                    for (int ni = 0; ni < 4; ++ni)
                        mma16816(acc[mi][ni], afr[mi], bfr[ni]);
            }
        }
    }

    // ---- epilogue: bias add, Z store, deterministic BN partial sums ----
    const int grp = lane >> 2, t4 = lane & 3;
    float s1[8], s2[8];
#pragma unroll
    for (int q = 0; q < 8; ++q) { s1[q] = 0.f; s2[q] = 0.f; }

#pragma unroll
    for (int ni = 0; ni < 4; ++ni) {
        const int j = m0 + wj * 32 + ni * 8 + 2 * t4;
        const float bv0 = bias[j], bv1 = bias[j + 1];
#pragma unroll
        for (int mi = 0; mi < 4; ++mi) {
            const size_t r0 = n0 + wi * 64 + mi * 16 + grp;
            const size_t r1 = r0 + 8;
            float z0 = acc[mi][ni][0] + bv0;
            float z1 = acc[mi][ni][1] + bv1;
            float z2 = acc[mi][ni][2] + bv0;
            float z3 = acc[mi][ni][3] + bv1;
            *(float2*)(Z + r0 * MTOT + j) = make_float2(z0, z1);
            *(float2*)(Z + r1 * MTOT + j) = make_float2(z2, z3);
            s1[ni * 2 + 0] += z0 + z2;
            s1[ni * 2 + 1] += z1 + z3;
            s2[ni * 2 + 0] = fmaf(z0, z0, fmaf(z2, z2, s2[ni * 2 + 0]));
            s2[ni * 2 + 1] = fmaf(z1, z1, fmaf(z3, z3, s2[ni * 2 + 1]));
        }
    }
    // reduce over the 8 groups (rows) within the warp
#pragma unroll
    for (int off = 16; off >= 4; off >>= 1)
#pragma unroll
        for (int q = 0; q < 8; ++q) {
            s1[q] += __shfl_down_sync(0xFFFFFFFFu, s1[q], off);
            s2[q] += __shfl_down_sync(0xFFFFFFFFu, s2[q], off);
        }
    if (lane < 4) {
#pragma unroll
        for (int ni = 0; ni < 4; ++ni)
#pragma unroll
            for (int c = 0; c < 2; ++c) {
                sred[wid][ni * 8 + 2 * lane + c]      = s1[ni * 2 + c];
                sred[wid][32 + ni * 8 + 2 * lane + c] = s2[ni * 2 + c];
            }
    }
    __syncthreads();
    if (tid < 128) {
        const int wjj = tid >> 5, cl = tid & 31;
        float a1 = sred[wjj][cl]      + sred[wjj + 4][cl];
        float a2 = sred[wjj][32 + cl] + sred[wjj + 4][32 + cl];
        ps1[(size_t)blockIdx.y * MTOT + m0 + tid] = a1;
        ps2[(size_t)blockIdx.y * MTOT + m0 + tid] = a2;
    }
}

// ---------------- BN finalize: reduce partials -> scale/shift ----------------
__global__ __launch_bounds__(256) void bn_finalize_kernel(const float* __restrict__ ps1,
                                                          const float* __restrict__ ps2,
                                                          const float* __restrict__ g,
                                                          const float* __restrict__ be,
                                                          float* __restrict__ sc,
                                                          float* __restrict__ sh, int M) {
    const int m = blockIdx.x;
    const int tid = threadIdx.x;
    float s1 = 0.f, s2 = 0.f;
    for (int t = tid; t < PTILES; t += 256) {
        s1 += ps1[(size_t)t * M + m];
        s2 += ps2[(size_t)t * M + m];
    }
    __shared__ float r1[8], r2[8];
#pragma unroll
    for (int off = 16; off; off >>= 1) {
        s1 += __shfl_down_sync(0xFFFFFFFFu, s1, off);
        s2 += __shfl_down_sync(0xFFFFFFFFu, s2, off);
    }
    if ((tid & 31) == 0) { r1[tid >> 5] = s1; r2[tid >> 5] = s2; }
    __syncthreads();
    if (tid < 32) {
        s1 = (tid < 8) ? r1[tid] : 0.f;
        s2 = (tid < 8) ? r2[tid] : 0.f;
#pragma unroll
        for (int off = 4; off; off >>= 1) {
            s1 += __shfl_down_sync(0xFFFFFFFFu, s1, off);
            s2 += __shfl_down_sync(0xFFFFFFFFu, s2, off);
        }
        if (tid == 0) {
            const float inv = 1.f / (float)NTOT;
            float mu  = s1 * inv;
            float var = s2 * inv - mu * mu;
            float r   = rsqrtf(var + BNEPS);
            float s   = r * g[m];
            sc[m] = s;
            sh[m] = be[m] - mu * s;
        }
    }
}

// ---------------- final: BN3+ReLU + transpose [n][128] -> out [b][128][NY] ----------------
__global__ __launch_bounds__(256) void final_kernel(const float* __restrict__ Z3,
                                                    float* __restrict__ out) {
    __shared__ float tile[32][33];
    const int b = blockIdx.z;
    const int n0 = blockIdx.x * 32;
    const int c0 = blockIdx.y * 32;
    const int tx = threadIdx.x, ty = threadIdx.y;   // 32 x 8
    const float sc = g_sc3[c0 + tx], sh = g_sh3[c0 + tx];
#pragma unroll
    for (int r = 0; r < 4; ++r) {
        int n = n0 + ty + 8 * r;
        float v = Z3[((size_t)b * NY + n) * C3 + c0 + tx];
        tile[ty + 8 * r][tx] = fmaxf(fmaf(v, sc, sh), 0.f);
    }
    __syncthreads();
#pragma unroll
    for (int r = 0; r < 4; ++r) {
        int cl = ty + 8 * r;
        out[((size_t)b * C3 + c0 + cl) * NY + n0 + tx] = tile[tx][cl];
    }
}

// ---------------- host launcher ----------------
extern "C" void kernel_launch(void* const* d_in, const int* in_sizes, int n_in,
                              void* d_out, int out_size) {
    (void)in_sizes; (void)n_in; (void)out_size;
    const float* yp = (const float*)d_in[0];
    const float* yf = (const float*)d_in[1];
    const float* xp = (const float*)d_in[2];
    const float* xf = (const float*)d_in[3];
    const float* W1 = (const float*)d_in[4];
    const float* b1 = (const float*)d_in[5];
    const float* g1 = (const float*)d_in[6];
    const float* be1 = (const float*)d_in[7];
    const float* W2 = (const float*)d_in[8];
    const float* b2 = (const float*)d_in[9];
    const float* g2 = (const float*)d_in[10];
    const float* be2 = (const float*)d_in[11];
    const float* W3 = (const float*)d_in[12];
    const float* b3 = (const float*)d_in[13];
    const float* g3 = (const float*)d_in[14];
    const float* be3 = (const float*)d_in[15];
    float* out = (float*)d_out;

    unsigned short *x1h, *x1l, *x2h, *x2l, *x3h, *x3l;
    unsigned short *w1h, *w1l, *w2h, *w2l, *w3h, *w3l;
    float *z1, *z2, *z3, *ps1, *ps2;
    float *sc1, *sh1, *sc2, *sh2, *sc3, *sh3;
    cudaGetSymbolAddress((void**)&x1h, g_x1h); cudaGetSymbolAddress((void**)&x1l, g_x1l);
    cudaGetSymbolAddress((void**)&x2h, g_x2h); cudaGetSymbolAddress((void**)&x2l, g_x2l);
    cudaGetSymbolAddress((void**)&x3h, g_x3h); cudaGetSymbolAddress((void**)&x3l, g_x3l);
    cudaGetSymbolAddress((void**)&w1h, g_w1h); cudaGetSymbolAddress((void**)&w1l, g_w1l);
    cudaGetSymbolAddress((void**)&w2h, g_w2h); cudaGetSymbolAddress((void**)&w2l, g_w2l);
    cudaGetSymbolAddress((void**)&w3h, g_w3h); cudaGetSymbolAddress((void**)&w3l, g_w3l);
    cudaGetSymbolAddress((void**)&z1, g_z1);
    cudaGetSymbolAddress((void**)&z2, g_z2);
    cudaGetSymbolAddress((void**)&z3, g_z3);
    cudaGetSymbolAddress((void**)&ps1, g_ps1); cudaGetSymbolAddress((void**)&ps2, g_ps2);
    cudaGetSymbolAddress((void**)&sc1, g_sc1); cudaGetSymbolAddress((void**)&sh1, g_sh1);
    cudaGetSymbolAddress((void**)&sc2, g_sc2); cudaGetSymbolAddress((void**)&sh2, g_sh2);
    cudaGetSymbolAddress((void**)&sc3, g_sc3); cudaGetSymbolAddress((void**)&sh3, g_sh3);

    // 1) KNN                                   (launch 1)
    knn_kernel<<<dim3(NY / 256, NB), 256>>>(yp, xp);
    // 2) interp + concat -> X1 hi/lo           (launch 2)
    interp_split_kernel<<<NTOT / 4, 384>>>(yf, xf);
    // 3) all weight splits in ONE launch       (launch 3)
    prep_w_all_kernel<<<(NWTOT + 255) / 256, 256>>>(W1, W2, W3);
    // 4) layer 1 GEMM                          (launch 4 <- ncu capture slot)
    gemm_mma_kernel<CIN0, C1><<<dim3(C1 / 128, PTILES), 256>>>(
        x1h, x1l, w1h, w1l, b1, z1, ps1, ps2);
    bn_finalize_kernel<<<C1, 256>>>(ps1, ps2, g1, be1, sc1, sh1, C1);
    prep_x_kernel<C1><<<(NTOT * C1 / 4) / 256, 256>>>(z1, sc1, sh1, x2h, x2l);
    // 5) layer 2
    gemm_mma_kernel<C1, C2><<<dim3(C2 / 128, PTILES), 256>>>(
        x2h, x2l, w2h, w2l, b2, z2, ps1, ps2);
    bn_finalize_kernel<<<C2, 256>>>(ps1, ps2, g2, be2, sc2, sh2, C2);
    prep_x_kernel<C2><<<(NTOT * C2 / 4) / 256, 256>>>(z2, sc2, sh2, x3h, x3l);
    // 6) layer 3
    gemm_mma_kernel<C2, C3><<<dim3(C3 / 128, PTILES), 256>>>(
        x3h, x3l, w3h, w3l, b3, z3, ps1, ps2);
    bn_finalize_kernel<<<C3, 256>>>(ps1, ps2, g3, be3, sc3, sh3, C3);
    // 7) final BN3+ReLU + transpose to [b][c][n]
    final_kernel<<<dim3(NY / 32, C3 / 32, NB), dim3(32, 8)>>>(z3, out);
}

// round 14
// speedup vs baseline: 1.2315x; 1.2118x over previous
#include <cuda_runtime.h>
#include <cuda_fp16.h>
#include <cstdint>

// Problem constants
#define NB   4
#define NY   16384
#define NX   4096
#define CY   128
#define CX   256
#define CIN0 384          // CY + CX
#define C1   512
#define C2   256
#define C3   128
#define KNN_K 3
#define EPSW  1e-8f
#define BNEPS 1e-5f
#define NTOT (NB * NY)          // 65536 points
#define PTILES (NTOT / 128)     // 512 point tiles

// ---------------- scratch (device globals; no allocation) ----------------
__device__ int            g_idx[(size_t)NTOT * KNN_K];
__device__ float          g_wts[(size_t)NTOT * KNN_K];
__device__ unsigned short g_x1h[(size_t)NTOT * CIN0], g_x1l[(size_t)NTOT * CIN0];
__device__ unsigned short g_x2h[(size_t)NTOT * C1],   g_x2l[(size_t)NTOT * C1];
__device__ unsigned short g_x3h[(size_t)NTOT * C2],   g_x3l[(size_t)NTOT * C2];
__device__ float          g_z1[(size_t)NTOT * C1];
__device__ float          g_z2[(size_t)NTOT * C2];
__device__ float          g_z3[(size_t)NTOT * C3];
__device__ unsigned short g_w1[C1 * CIN0];
__device__ unsigned short g_w2[C2 * C1];
__device__ unsigned short g_w3[C3 * C2];
__device__ float          g_ps1[PTILES * C1], g_ps2[PTILES * C1];
__device__ float          g_sc1[C1], g_sh1[C1];
__device__ float          g_sc2[C2], g_sh2[C2];
__device__ float          g_sc3[C3], g_sh3[C3];

// ================= helpers (baseline PTX only — valid on plain sm_103) ====
__device__ __forceinline__ uint32_t smem_to_u32(const void* p) {
    uint32_t a;
    asm("{ .reg .u64 t; cvta.to.shared.u64 t, %1; cvt.u32.u64 %0, t; }" : "=r"(a) : "l"(p));
    return a;
}
__device__ __forceinline__ void cp_async16(uint32_t dst, const void* src) {
    asm volatile("cp.async.ca.shared.global [%0], [%1], 16;" :: "r"(dst), "l"(src));
}
__device__ __forceinline__ void cp_async_commit_wait() {
    asm volatile("cp.async.commit_group;" ::: "memory");
    asm volatile("cp.async.wait_group 0;" ::: "memory");
}
__device__ __forceinline__ void ldm_x4(uint32_t* r, uint32_t addr) {
    asm volatile("ldmatrix.sync.aligned.m8n8.x4.shared.b16 {%0,%1,%2,%3}, [%4];"
                 : "=r"(r[0]), "=r"(r[1]), "=r"(r[2]), "=r"(r[3]) : "r"(addr));
}
__device__ __forceinline__ void ldm_x2(uint32_t* r, uint32_t addr) {
    asm volatile("ldmatrix.sync.aligned.m8n8.x2.shared.b16 {%0,%1}, [%2];"
                 : "=r"(r[0]), "=r"(r[1]) : "r"(addr));
}
__device__ __forceinline__ void mma16816_f16(float* d, const uint32_t* a, const uint32_t* b) {
    asm volatile("mma.sync.aligned.m16n8k16.row.col.f32.f16.f16.f32 "
                 "{%0,%1,%2,%3}, {%4,%5,%6,%7}, {%8,%9}, {%0,%1,%2,%3};"
                 : "+f"(d[0]), "+f"(d[1]), "+f"(d[2]), "+f"(d[3])
                 : "r"(a[0]), "r"(a[1]), "r"(a[2]), "r"(a[3]), "r"(b[0]), "r"(b[1]));
}
// fp16 split: v = hi + lo + O(2^-24 * v)
__device__ __forceinline__ void split_f16(float v, unsigned short& hi, unsigned short& lo) {
    __half h = __float2half_rn(v);
    float hv = __half2float(h);
    __half l = __float2half_rn(v - hv);
    hi = reinterpret_cast<unsigned short&>(h);
    lo = reinterpret_cast<unsigned short&>(l);
}
__device__ __forceinline__ unsigned short f16_of(float v) {
    __half h = __float2half_rn(v);
    return reinterpret_cast<unsigned short&>(h);
}

// ---------------- KNN (numerics frozen — matches reference op-for-op) ----------------
__global__ __launch_bounds__(256) void knn_kernel(const float* __restrict__ yp,
                                                  const float* __restrict__ xp) {
    __shared__ float4 xs[2048];
    const int b = blockIdx.y;
    const int n = blockIdx.x * 256 + threadIdx.x;

    const float* ypt = yp + ((size_t)b * NY + n) * 3;
    const float yx = ypt[0], yy = ypt[1], yz = ypt[2];
    const float sy = __fadd_rn(__fadd_rn(__fmul_rn(yx, yx), __fmul_rn(yy, yy)),
                               __fmul_rn(yz, yz));

    float d0 = 3.4e38f, d1 = 3.4e38f, d2 = 3.4e38f;
    int   i0 = 0, i1 = 0, i2 = 0;

    for (int h = 0; h < 2; ++h) {
        const float* xpb = xp + ((size_t)b * NX + h * 2048) * 3;
        for (int t = threadIdx.x; t < 2048; t += 256) {
            float ax = xpb[t * 3 + 0];
            float ay = xpb[t * 3 + 1];
            float az = xpb[t * 3 + 2];
            float sx = __fadd_rn(__fadd_rn(__fmul_rn(ax, ax), __fmul_rn(ay, ay)),
                                 __fmul_rn(az, az));
            xs[t] = make_float4(ax, ay, az, sx);
        }
        __syncthreads();
        const int base = h * 2048;
#pragma unroll 4
        for (int j = 0; j < 2048; ++j) {
            float4 p = xs[j];
            float dot = __fmaf_rn(yz, p.z, __fmaf_rn(yy, p.y, __fmul_rn(yx, p.x)));
            float t = __fsub_rn(__fadd_rn(sy, p.w), __fmul_rn(2.f, dot));
            if (t < d2) {
                int gi = base + j;
                if (t < d1) {
                    d2 = d1; i2 = i1;
                    if (t < d0) { d1 = d0; i1 = i0; d0 = t; i0 = gi; }
                    else        { d1 = t;  i1 = gi; }
                } else { d2 = t; i2 = gi; }
            }
        }
        __syncthreads();
    }

    float w0 = __fdiv_rn(1.f, __fadd_rn(d0, EPSW));
    float w1 = __fdiv_rn(1.f, __fadd_rn(d1, EPSW));
    float w2 = __fdiv_rn(1.f, __fadd_rn(d2, EPSW));
    float ws = __fadd_rn(__fadd_rn(w0, w1), w2);
    const size_t o = ((size_t)b * NY + n) * 3;
    g_idx[o + 0] = i0; g_idx[o + 1] = i1; g_idx[o + 2] = i2;
    g_wts[o + 0] = __fdiv_rn(w0, ws);
    g_wts[o + 1] = __fdiv_rn(w1, ws);
    g_wts[o + 2] = __fdiv_rn(w2, ws);
}

// ---------------- interp + concat -> X1 fp16 hi/lo, point-major [n][384] ----------------
__global__ __launch_bounds__(384) void interp_split_kernel(const float* __restrict__ yf,
                                                           const float* __restrict__ xf) {
    const int tid = threadIdx.x;            // 0..383 (== channel)
    size_t n = (size_t)blockIdx.x * 4;
    for (int r = 0; r < 4; ++r, ++n) {
        float v;
        if (tid < CY) {
            v = yf[n * CY + tid];
        } else {
            const size_t o = n * 3;
            float w0 = g_wts[o], w1 = g_wts[o + 1], w2 = g_wts[o + 2];
            int   j0 = g_idx[o], j1 = g_idx[o + 1], j2 = g_idx[o + 2];
            const int b = (int)(n >> 14);
            const float* xfb = xf + (size_t)b * NX * CX;
            const int c = tid - CY;
            float t0 = __fmul_rn(xfb[(size_t)j0 * CX + c], w0);
            float t1 = __fmul_rn(xfb[(size_t)j1 * CX + c], w1);
            float t2 = __fmul_rn(xfb[(size_t)j2 * CX + c], w2);
            v = __fadd_rn(__fadd_rn(t0, t1), t2);
        }
        unsigned short hi, lo;
        split_f16(v, hi, lo);
        g_x1h[n * CIN0 + tid] = hi;
        g_x1l[n * CIN0 + tid] = lo;
    }
}

// ---------------- all weights fp32 -> single fp16 in ONE launch ----------------
#define NW1 (C1 * CIN0)    // 196608
#define NW2 (C2 * C1)      // 131072
#define NW3 (C3 * C2)      // 32768
#define NWTOT (NW1 + NW2 + NW3)
__global__ __launch_bounds__(256) void prep_w_all_kernel(const float* __restrict__ W1,
                                                         const float* __restrict__ W2,
                                                         const float* __restrict__ W3) {
    int i = blockIdx.x * 256 + threadIdx.x;
    if (i >= NWTOT) return;
    const float* W; unsigned short* dst; int j;
    if (i < NW1)            { W = W1; dst = g_w1; j = i; }
    else if (i < NW1 + NW2) { W = W2; dst = g_w2; j = i - NW1; }
    else                    { W = W3; dst = g_w3; j = i - NW1 - NW2; }
    dst[j] = f16_of(W[j]);
}

// ---------------- BN+ReLU+split prepass: Z fp32 [n][C] -> X fp16 hi/lo [n][C] ----------------
template <int C>
__global__ __launch_bounds__(256) void prep_x_kernel(const float* __restrict__ Z,
                                                     const float* __restrict__ sc,
                                                     const float* __restrict__ sh,
                                                     unsigned short* __restrict__ Xh,
                                                     unsigned short* __restrict__ Xl) {
    size_t i = (size_t)blockIdx.x * 256 + threadIdx.x;   // float4 index
    int c0 = (int)((i * 4) & (C - 1));
    float4 v = ((const float4*)Z)[i];
    float r0 = fmaxf(fmaf(v.x, sc[c0 + 0], sh[c0 + 0]), 0.f);
    float r1 = fmaxf(fmaf(v.y, sc[c0 + 1], sh[c0 + 1]), 0.f);
    float r2 = fmaxf(fmaf(v.z, sc[c0 + 2], sh[c0 + 2]), 0.f);
    float r3 = fmaxf(fmaf(v.w, sc[c0 + 3], sh[c0 + 3]), 0.f);
    ushort4 h, l;
    split_f16(r0, h.x, l.x); split_f16(r1, h.y, l.y);
    split_f16(r2, h.z, l.z); split_f16(r3, h.w, l.w);
    ((ushort4*)Xh)[i] = h;
    ((ushort4*)Xl)[i] = l;
}

// ---------------- mma.sync fp16 split-X GEMM (2 passes: Xh*W + Xl*W) ----------------
// Z[n][m] = sum_k X[n][k]*W[m][k] + bias[m];  X = Xh+Xl fp16, W single fp16.
// CTA: 128 points x 128 channels. 8 warps (2 point x 4 channel), warp tile 64x32.
// K chunk = 32. SMEM rows padded to 40 fp16 (80 B). 3 operand tiles.
#define TSTRIDE 80            // bytes per SMEM row
#define TILE_B  10240         // bytes per tile (128 rows * 80)
#define XH_OFF  0
#define XL_OFF  10240
#define W_OFF   20480

template <int KD, int MTOT>
__global__ __launch_bounds__(256) void gemm_mma_kernel(
    const unsigned short* __restrict__ Xh, const unsigned short* __restrict__ Xl,
    const unsigned short* __restrict__ Wm,
    const float* __restrict__ bias, float* __restrict__ Z,
    float* __restrict__ ps1, float* __restrict__ ps2) {
    __shared__ __align__(16) unsigned char stile[3 * TILE_B];
    __shared__ float sred[8][64];            // [warp][ch 0..31 = s1, 32..63 = s2]
    const uint32_t sm = smem_to_u32(stile);

    const int tid = threadIdx.x;
    const int wid = tid >> 5, lane = tid & 31;
    const int wi = wid >> 2;                 // point-warp (0..1)
    const int wj = wid & 3;                  // channel-warp (0..3)
    const int m0 = blockIdx.x * 128;         // channel base
    const size_t n0 = (size_t)blockIdx.y * 128;  // point base

    const unsigned short* srcs[3] = {
        Xh + n0 * KD, Xl + n0 * KD, Wm + (size_t)m0 * KD };

    float acc[4][4][4];
#pragma unroll
    for (int mi = 0; mi < 4; ++mi)
#pragma unroll
        for (int ni = 0; ni < 4; ++ni)
#pragma unroll
            for (int q = 0; q < 4; ++q) acc[mi][ni][q] = 0.f;

    // precomputed ldmatrix lane addresses (byte offsets w/o kstep)
    const uint32_t aRow = (uint32_t)(wi * 64 + (lane & 7) + ((lane >> 3) & 1) * 8);
    const uint32_t aK   = (uint32_t)((lane >> 4) * 16);
    const uint32_t bRow = (uint32_t)(wj * 32 + (lane & 7));
    const uint32_t bK   = (uint32_t)(((lane >> 3) & 1) * 16);

    for (int ck = 0; ck < KD / 32; ++ck) {
        if (ck) __syncthreads();             // all warps done with prev tile
        const int k0 = ck * 32;
#pragma unroll
        for (int t = 0; t < 3; ++t) {
            const unsigned short* src = srcs[t];
            const uint32_t dstb = sm + t * TILE_B;
#pragma unroll
            for (int q = 0; q < 2; ++q) {
                int idx = tid + q * 256;
                int row = idx >> 2, ks = idx & 3;
                cp_async16(dstb + row * TSTRIDE + ks * 16,
                           src + (size_t)row * KD + k0 + ks * 8);
            }
        }
        cp_async_commit_wait();
        __syncthreads();

        const uint32_t bBase = sm + W_OFF;
#pragma unroll
        for (int p = 0; p < 2; ++p) {
            const uint32_t aBase = sm + (p ? XL_OFF : XH_OFF);
#pragma unroll
            for (int kk = 0; kk < 2; ++kk) {
                uint32_t afr[4][4], bfr[4][2];
#pragma unroll
                for (int mi = 0; mi < 4; ++mi)
                    ldm_x4(afr[mi], aBase + (aRow + mi * 16) * TSTRIDE + kk * 32 + aK);
#pragma unroll
                for (int ni = 0; ni < 4; ++ni)
                    ldm_x2(bfr[ni], bBase + (bRow + ni * 8) * TSTRIDE + kk * 32 + bK);
#pragma unroll
                for (int mi = 0; mi < 4; ++mi)
#pragma unroll
                    for (int ni = 0; ni < 4; ++ni)
                        mma16816_f16(acc[mi][ni], afr[mi], bfr[ni]);
            }
        }
    }

    // ---- epilogue: bias add, Z store, deterministic BN partial sums ----
    const int grp = lane >> 2, t4 = lane & 3;
    float s1[8], s2[8];
#pragma unroll
    for (int q = 0; q < 8; ++q) { s1[q] = 0.f; s2[q] = 0.f; }

#pragma unroll
    for (int ni = 0; ni < 4; ++ni) {
        const int j = m0 + wj * 32 + ni * 8 + 2 * t4;
        const float bv0 = bias[j], bv1 = bias[j + 1];
#pragma unroll
        for (int mi = 0; mi < 4; ++mi) {
            const size_t r0 = n0 + wi * 64 + mi * 16 + grp;
            const size_t r1 = r0 + 8;
            float z0 = acc[mi][ni][0] + bv0;
            float z1 = acc[mi][ni][1] + bv1;
            float z2 = acc[mi][ni][2] + bv0;
            float z3 = acc[mi][ni][3] + bv1;
            *(float2*)(Z + r0 * MTOT + j) = make_float2(z0, z1);
            *(float2*)(Z + r1 * MTOT + j) = make_float2(z2, z3);
            s1[ni * 2 + 0] += z0 + z2;
            s1[ni * 2 + 1] += z1 + z3;
            s2[ni * 2 + 0] = fmaf(z0, z0, fmaf(z2, z2, s2[ni * 2 + 0]));
            s2[ni * 2 + 1] = fmaf(z1, z1, fmaf(z3, z3, s2[ni * 2 + 1]));
        }
    }
    // reduce over the 8 groups (rows) within the warp
#pragma unroll
    for (int off = 16; off >= 4; off >>= 1)
#pragma unroll
        for (int q = 0; q < 8; ++q) {
            s1[q] += __shfl_down_sync(0xFFFFFFFFu, s1[q], off);
            s2[q] += __shfl_down_sync(0xFFFFFFFFu, s2[q], off);
        }
    if (lane < 4) {
#pragma unroll
        for (int ni = 0; ni < 4; ++ni)
#pragma unroll
            for (int c = 0; c < 2; ++c) {
                sred[wid][ni * 8 + 2 * lane + c]      = s1[ni * 2 + c];
                sred[wid][32 + ni * 8 + 2 * lane + c] = s2[ni * 2 + c];
            }
    }
    __syncthreads();
    if (tid < 128) {
        const int wjj = tid >> 5, cl = tid & 31;
        float a1 = sred[wjj][cl]      + sred[wjj + 4][cl];
        float a2 = sred[wjj][32 + cl] + sred[wjj + 4][32 + cl];
        ps1[(size_t)blockIdx.y * MTOT + m0 + tid] = a1;
        ps2[(size_t)blockIdx.y * MTOT + m0 + tid] = a2;
    }
}

// ---------------- BN finalize: reduce partials -> scale/shift ----------------
__global__ __launch_bounds__(256) void bn_finalize_kernel(const float* __restrict__ ps1,
                                                          const float* __restrict__ ps2,
                                                          const float* __restrict__ g,
                                                          const float* __restrict__ be,
                                                          float* __restrict__ sc,
                                                          float* __restrict__ sh, int M) {
    const int m = blockIdx.x;
    const int tid = threadIdx.x;
    float s1 = 0.f, s2 = 0.f;
    for (int t = tid; t < PTILES; t += 256) {
        s1 += ps1[(size_t)t * M + m];
        s2 += ps2[(size_t)t * M + m];
    }
    __shared__ float r1[8], r2[8];
#pragma unroll
    for (int off = 16; off; off >>= 1) {
        s1 += __shfl_down_sync(0xFFFFFFFFu, s1, off);
        s2 += __shfl_down_sync(0xFFFFFFFFu, s2, off);
    }
    if ((tid & 31) == 0) { r1[tid >> 5] = s1; r2[tid >> 5] = s2; }
    __syncthreads();
    if (tid < 32) {
        s1 = (tid < 8) ? r1[tid] : 0.f;
        s2 = (tid < 8) ? r2[tid] : 0.f;
#pragma unroll
        for (int off = 4; off; off >>= 1) {
            s1 += __shfl_down_sync(0xFFFFFFFFu, s1, off);
            s2 += __shfl_down_sync(0xFFFFFFFFu, s2, off);
        }
        if (tid == 0) {
            const float inv = 1.f / (float)NTOT;
            float mu  = s1 * inv;
            float var = s2 * inv - mu * mu;
            float r   = rsqrtf(var + BNEPS);
            float s   = r * g[m];
            sc[m] = s;
            sh[m] = be[m] - mu * s;
        }
    }
}

// ---------------- final: BN3+ReLU + transpose [n][128] -> out [b][128][NY] ----------------
__global__ __launch_bounds__(256) void final_kernel(const float* __restrict__ Z3,
                                                    float* __restrict__ out) {
    __shared__ float tile[32][33];
    const int b = blockIdx.z;
    const int n0 = blockIdx.x * 32;
    const int c0 = blockIdx.y * 32;
    const int tx = threadIdx.x, ty = threadIdx.y;   // 32 x 8
    const float sc = g_sc3[c0 + tx], sh = g_sh3[c0 + tx];
#pragma unroll
    for (int r = 0; r < 4; ++r) {
        int n = n0 + ty + 8 * r;
        float v = Z3[((size_t)b * NY + n) * C3 + c0 + tx];
        tile[ty + 8 * r][tx] = fmaxf(fmaf(v, sc, sh), 0.f);
    }
    __syncthreads();
#pragma unroll
    for (int r = 0; r < 4; ++r) {
        int cl = ty + 8 * r;
        out[((size_t)b * C3 + c0 + cl) * NY + n0 + tx] = tile[tx][cl];
    }
}

// ---------------- host launcher ----------------
extern "C" void kernel_launch(void* const* d_in, const int* in_sizes, int n_in,
                              void* d_out, int out_size) {
    (void)in_sizes; (void)n_in; (void)out_size;
    const float* yp = (const float*)d_in[0];
    const float* yf = (const float*)d_in[1];
    const float* xp = (const float*)d_in[2];
    const float* xf = (const float*)d_in[3];
    const float* W1 = (const float*)d_in[4];
    const float* b1 = (const float*)d_in[5];
    const float* g1 = (const float*)d_in[6];
    const float* be1 = (const float*)d_in[7];
    const float* W2 = (const float*)d_in[8];
    const float* b2 = (const float*)d_in[9];
    const float* g2 = (const float*)d_in[10];
    const float* be2 = (const float*)d_in[11];
    const float* W3 = (const float*)d_in[12];
    const float* b3 = (const float*)d_in[13];
    const float* g3 = (const float*)d_in[14];
    const float* be3 = (const float*)d_in[15];
    float* out = (float*)d_out;

    unsigned short *x1h, *x1l, *x2h, *x2l, *x3h, *x3l;
    unsigned short *w1, *w2, *w3;
    float *z1, *z2, *z3, *ps1, *ps2;
    float *sc1, *sh1, *sc2, *sh2, *sc3, *sh3;
    cudaGetSymbolAddress((void**)&x1h, g_x1h); cudaGetSymbolAddress((void**)&x1l, g_x1l);
    cudaGetSymbolAddress((void**)&x2h, g_x2h); cudaGetSymbolAddress((void**)&x2l, g_x2l);
    cudaGetSymbolAddress((void**)&x3h, g_x3h); cudaGetSymbolAddress((void**)&x3l, g_x3l);
    cudaGetSymbolAddress((void**)&w1, g_w1);
    cudaGetSymbolAddress((void**)&w2, g_w2);
    cudaGetSymbolAddress((void**)&w3, g_w3);
    cudaGetSymbolAddress((void**)&z1, g_z1);
    cudaGetSymbolAddress((void**)&z2, g_z2);
    cudaGetSymbolAddress((void**)&z3, g_z3);
    cudaGetSymbolAddress((void**)&ps1, g_ps1); cudaGetSymbolAddress((void**)&ps2, g_ps2);
    cudaGetSymbolAddress((void**)&sc1, g_sc1); cudaGetSymbolAddress((void**)&sh1, g_sh1);
    cudaGetSymbolAddress((void**)&sc2, g_sc2); cudaGetSymbolAddress((void**)&sh2, g_sh2);
    cudaGetSymbolAddress((void**)&sc3, g_sc3); cudaGetSymbolAddress((void**)&sh3, g_sh3);

    // 1) KNN                                   (launch 1)
    knn_kernel<<<dim3(NY / 256, NB), 256>>>(yp, xp);
    // 2) interp + concat -> X1 hi/lo           (launch 2)
    interp_split_kernel<<<NTOT / 4, 384>>>(yf, xf);
    // 3) all weight fp16 in ONE launch         (launch 3)
    prep_w_all_kernel<<<(NWTOT + 255) / 256, 256>>>(W1, W2, W3);
    // 4) layer 1 GEMM                          (launch 4 <- ncu capture slot)
    gemm_mma_kernel<CIN0, C1><<<dim3(C1 / 128, PTILES), 256>>>(
        x1h, x1l, w1, b1, z1, ps1, ps2);
    bn_finalize_kernel<<<C1, 256>>>(ps1, ps2, g1, be1, sc1, sh1, C1);
    prep_x_kernel<C1><<<(NTOT * C1 / 4) / 256, 256>>>(z1, sc1, sh1, x2h, x2l);
    // 5) layer 2
    gemm_mma_kernel<C1, C2><<<dim3(C2 / 128, PTILES), 256>>>(
        x2h, x2l, w2, b2, z2, ps1, ps2);
    bn_finalize_kernel<<<C2, 256>>>(ps1, ps2, g2, be2, sc2, sh2, C2);
    prep_x_kernel<C2><<<(NTOT * C2 / 4) / 256, 256>>>(z2, sc2, sh2, x3h, x3l);
    // 6) layer 3
    gemm_mma_kernel<C2, C3><<<dim3(C3 / 128, PTILES), 256>>>(
        x3h, x3l, w3, b3, z3, ps1, ps2);
    bn_finalize_kernel<<<C3, 256>>>(ps1, ps2, g3, be3, sc3, sh3, C3);
    // 7) final BN3+ReLU + transpose to [b][c][n]
    final_kernel<<<dim3(NY / 32, C3 / 32, NB), dim3(32, 8)>>>(z3, out);
}